// round 15
// baseline (speedup 1.0000x reference)
#include <cuda_runtime.h>
#include <math.h>

#define NN   50000
#define EE   100000
#define GG   2048

typedef unsigned long long ull;

// ---------------- device scratch ----------------
__device__ float g_h[NN * 32];
__device__ __align__(16) float g_aggr[NN * 32];
__device__ __align__(16) float g_Y[(size_t)NN * 160];   // [node][j*32+o]
__device__ float g_pool[GG * 32];
__device__ float g_cnt[GG];

// weight tables
__device__ __align__(16) float P_MS[5120];   // pair-packed for k_init
__device__ float W_G[64 * 96];               // k-major GRU: [k][g] k<32->wi, k>=32->wh
__device__ float W_MS[32 * 160];             // k-major msg: [k][j*32+o]

// ---------------- f32x2 helpers ----------------
__device__ __forceinline__ ull ffma2(ull a, ull b, ull c) {
    ull d;
    asm("fma.rn.f32x2 %0, %1, %2, %3;" : "=l"(d) : "l"(a), "l"(b), "l"(c));
    return d;
}
__device__ __forceinline__ ull dup2(float w) {
    ull r;
    asm("mov.b64 %0, {%1, %1};" : "=l"(r) : "f"(w));
    return r;
}
__device__ __forceinline__ float flo(ull v) { return __uint_as_float((unsigned)v); }
__device__ __forceinline__ float fhi(ull v) { return __uint_as_float((unsigned)(v >> 32)); }

// ---------------- K_pack ----------------
__global__ void k_pack(const float* __restrict__ wi,     // [96,32]
                       const float* __restrict__ wh,     // [96,32]
                       const float* __restrict__ nn_w,   // [1024,4]
                       const float* __restrict__ nn_b) { // [1024]
    int gid = blockIdx.x * blockDim.x + threadIdx.x;
    if (gid < GG * 32) g_pool[gid] = 0.0f;
    if (gid < GG) g_cnt[gid] = 0.0f;

    if (gid < 6144) {                        // W_G
        int k = gid / 96, g = gid % 96;
        W_G[gid] = (k < 32) ? wi[g * 32 + k] : wh[g * 32 + (k - 32)];
    } else if (gid < 6144 + 5120) {          // W_MS
        int t2 = gid - 6144;
        int k = t2 / 160, jo = t2 % 160;
        int j = jo >> 5, o = jo & 31;
        W_MS[t2] = (j < 4) ? nn_w[(k * 32 + o) * 4 + j] : nn_b[k * 32 + o];
    } else if (gid < 11264 + 5120) {         // P_MS (pair-packed for k_init)
        int t2 = gid - 11264;
        int pos = t2 & 3;
        int tmp = t2 >> 2;
        int lane = tmp & 31;
        int j = (tmp >> 5) % 5;
        int i4 = (tmp >> 5) / 5;
        int i = i4 * 4 + pos;
        P_MS[t2] = (j < 4) ? nn_w[(i * 32 + lane) * 4 + j] : nn_b[i * 32 + lane];
    }
}

// ---------------- K_init (R5 version): h0 = relu(lin0); Y0; zero aggr ----------------
__global__ __launch_bounds__(256, 2) void k_init(const float* __restrict__ x,
                                                 const float* __restrict__ w,   // [32,11]
                                                 const float* __restrict__ b) { // [32]
    __shared__ __align__(16) float hsm[8][8][32];
    int t = threadIdx.x, wrp = t >> 5, lane = t & 31;
    int n0 = blockIdx.x * 64 + wrp * 8;
    float (*row)[32] = hsm[wrp];

    float bias = __ldg(&b[lane]);
    float wv[11];
#pragma unroll
    for (int f = 0; f < 11; f++) wv[f] = __ldg(&w[lane * 11 + f]);

    float hn[8];
#pragma unroll
    for (int n = 0; n < 8; n++) {
        int node = n0 + n;
        float s = bias;
        if (node < NN) {
#pragma unroll
            for (int f = 0; f < 11; f++) s += __ldg(&x[node * 11 + f]) * wv[f];
        }
        hn[n] = fmaxf(s, 0.0f);
        row[n][lane] = hn[n];
    }
    __syncwarp();

    ull y[8][5];
#pragma unroll
    for (int n = 0; n < 8; n++)
#pragma unroll
        for (int j = 0; j < 5; j++) y[n][j] = 0ull;

#pragma unroll
    for (int i4 = 0; i4 < 8; i4++) {
        ulonglong2 mw[5];
#pragma unroll
        for (int j = 0; j < 5; j++)
            mw[j] = *(const ulonglong2*)&P_MS[((i4 * 5 + j) * 32 + lane) * 4];
#pragma unroll
        for (int n = 0; n < 8; n++) {
            ulonglong2 h2 = *(const ulonglong2*)&row[n][i4 * 4];
#pragma unroll
            for (int j = 0; j < 5; j++) {
                y[n][j] = ffma2(h2.x, mw[j].x, y[n][j]);
                y[n][j] = ffma2(h2.y, mw[j].y, y[n][j]);
            }
        }
    }
#pragma unroll
    for (int n = 0; n < 8; n++) {
        int node = n0 + n;
        if (node >= NN) break;
        g_h[node * 32 + lane] = hn[n];
        g_aggr[node * 32 + lane] = 0.0f;
        float* yb = &g_Y[(size_t)node * 160];
#pragma unroll
        for (int j = 0; j < 5; j++) yb[j * 32 + lane] = flo(y[n][j]) + fhi(y[n][j]);
    }
}

// ---------------- K_edge (R14 version): 4 edges/warp, 8 lanes/edge, v4 RED ----------------
__global__ void k_edge(const int* __restrict__ ei,        // [2,E]
                       const float* __restrict__ ea) {    // [E,4]
    int gt   = blockIdx.x * blockDim.x + threadIdx.x;
    int wrp  = gt >> 5;
    int lane = gt & 31;
    int e    = wrp * 4 + (lane >> 3);
    int q    = lane & 7;
    if (e >= EE) return;

    int s = __ldg(&ei[e]);
    int d = __ldg(&ei[EE + e]);
    float4 a = __ldg(&reinterpret_cast<const float4*>(ea)[e]);

    const float4* yb = reinterpret_cast<const float4*>(g_Y + (size_t)s * 160);
    float4 v0 = __ldg(&yb[q]);
    float4 v1 = __ldg(&yb[8 + q]);
    float4 v2 = __ldg(&yb[16 + q]);
    float4 v3 = __ldg(&yb[24 + q]);
    float4 vb = __ldg(&yb[32 + q]);

    float4 m;
    m.x = vb.x + a.x * v0.x + a.y * v1.x + a.z * v2.x + a.w * v3.x;
    m.y = vb.y + a.x * v0.y + a.y * v1.y + a.z * v2.y + a.w * v3.y;
    m.z = vb.z + a.x * v0.z + a.y * v1.z + a.z * v2.z + a.w * v3.z;
    m.w = vb.w + a.x * v0.w + a.y * v1.w + a.z * v2.w + a.w * v3.w;

    float* dst = g_aggr + (size_t)d * 32 + q * 4;
    asm volatile("red.global.add.v4.f32 [%0], {%1, %2, %3, %4};"
                 :: "l"(dst), "f"(m.x), "f"(m.y), "f"(m.z), "f"(m.w)
                 : "memory");
}

// ---------------- K_node (R7 version): GEMM-tile, 8 warps x 8 nodes ----------------
// lane = output dim. sh rows 0-31 = m (k-major), rows 32-63 = h (k-major).
__global__ __launch_bounds__(256, 2) void k_node(const float* __restrict__ root_w, // [32,32]
                                                 const float* __restrict__ conv_b, // [32]
                                                 const float* __restrict__ bi,     // [96]
                                                 const float* __restrict__ bh,     // [96]
                                                 const int* __restrict__ batch,
                                                 int last) {
    __shared__ __align__(16) float sh[64][68];
    int t = threadIdx.x, wrp = t >> 5, lane = t & 31;
    int n0 = blockIdx.x * 64 + wrp * 8;
    int colbase = wrp * 8;

    // stage h (k-major) + keep in registers; prefetch aggr
    float hreg[8], areg[8];
#pragma unroll
    for (int n = 0; n < 8; n++) {
        int node = n0 + n;
        hreg[n] = (node < NN) ? g_h[node * 32 + lane] : 0.0f;
        sh[32 + lane][colbase + n] = hreg[n];
    }
#pragma unroll
    for (int n = 0; n < 8; n++) {
        int node = n0 + n;
        areg[n] = (node < NN) ? __ldg(&g_aggr[node * 32 + lane]) : 0.0f;
    }
    __syncwarp();

    // --- root matvec: R[o=lane] = sum_k h[k]*root_w[k][o] ---
    ull R[4];
#pragma unroll
    for (int q = 0; q < 4; q++) R[q] = 0ull;
#pragma unroll 8
    for (int k = 0; k < 32; k++) {
        ulonglong2 o01 = *(const ulonglong2*)&sh[32 + k][colbase];
        ulonglong2 o23 = *(const ulonglong2*)&sh[32 + k][colbase + 4];
        ull w2 = dup2(__ldg(&root_w[k * 32 + lane]));
        R[0] = ffma2(o01.x, w2, R[0]);
        R[1] = ffma2(o01.y, w2, R[1]);
        R[2] = ffma2(o23.x, w2, R[2]);
        R[3] = ffma2(o23.y, w2, R[3]);
    }
    float cb = __ldg(&conv_b[lane]);
#pragma unroll
    for (int n = 0; n < 8; n++) {
        float r = (n & 1) ? fhi(R[n >> 1]) : flo(R[n >> 1]);
        float m = fmaxf(r + areg[n] + cb, 0.0f);
        sh[lane][colbase + n] = m;            // m k-major, rows 0-31
        int node = n0 + n;
        if (node < NN) g_aggr[node * 32 + lane] = 0.0f;   // pre-zero for next round
    }
    __syncwarp();

    // --- fused GRU: A=r-gate, B=z-gate, C=inn (m-part), D=hn (h-part) ---
    ull A[4], B[4], C[4], D[4];
#pragma unroll
    for (int q = 0; q < 4; q++) { A[q] = B[q] = C[q] = D[q] = 0ull; }
#pragma unroll 8
    for (int k = 0; k < 32; k++) {            // m rows
        ulonglong2 o01 = *(const ulonglong2*)&sh[k][colbase];
        ulonglong2 o23 = *(const ulonglong2*)&sh[k][colbase + 4];
        ull wr = dup2(__ldg(&W_G[k * 96 + lane]));
        ull wz = dup2(__ldg(&W_G[k * 96 + 32 + lane]));
        ull wn = dup2(__ldg(&W_G[k * 96 + 64 + lane]));
        A[0] = ffma2(o01.x, wr, A[0]); A[1] = ffma2(o01.y, wr, A[1]);
        A[2] = ffma2(o23.x, wr, A[2]); A[3] = ffma2(o23.y, wr, A[3]);
        B[0] = ffma2(o01.x, wz, B[0]); B[1] = ffma2(o01.y, wz, B[1]);
        B[2] = ffma2(o23.x, wz, B[2]); B[3] = ffma2(o23.y, wz, B[3]);
        C[0] = ffma2(o01.x, wn, C[0]); C[1] = ffma2(o01.y, wn, C[1]);
        C[2] = ffma2(o23.x, wn, C[2]); C[3] = ffma2(o23.y, wn, C[3]);
    }
#pragma unroll 8
    for (int k = 32; k < 64; k++) {           // h rows
        ulonglong2 o01 = *(const ulonglong2*)&sh[k][colbase];
        ulonglong2 o23 = *(const ulonglong2*)&sh[k][colbase + 4];
        ull wr = dup2(__ldg(&W_G[k * 96 + lane]));
        ull wz = dup2(__ldg(&W_G[k * 96 + 32 + lane]));
        ull wn = dup2(__ldg(&W_G[k * 96 + 64 + lane]));
        A[0] = ffma2(o01.x, wr, A[0]); A[1] = ffma2(o01.y, wr, A[1]);
        A[2] = ffma2(o23.x, wr, A[2]); A[3] = ffma2(o23.y, wr, A[3]);
        B[0] = ffma2(o01.x, wz, B[0]); B[1] = ffma2(o01.y, wz, B[1]);
        B[2] = ffma2(o23.x, wz, B[2]); B[3] = ffma2(o23.y, wz, B[3]);
        D[0] = ffma2(o01.x, wn, D[0]); D[1] = ffma2(o01.y, wn, D[1]);
        D[2] = ffma2(o23.x, wn, D[2]); D[3] = ffma2(o23.y, wn, D[3]);
    }

    float bir = __ldg(&bi[lane]), biz = __ldg(&bi[lane + 32]), bin = __ldg(&bi[lane + 64]);
    float bhr = __ldg(&bh[lane]), bhz = __ldg(&bh[lane + 32]), bhn = __ldg(&bh[lane + 64]);

    float hn[8];
#pragma unroll
    for (int n = 0; n < 8; n++) {
        int q = n >> 1;
        float ga = (n & 1) ? fhi(A[q]) : flo(A[q]);
        float gb = (n & 1) ? fhi(B[q]) : flo(B[q]);
        float gc = (n & 1) ? fhi(C[q]) : flo(C[q]);
        float gd = (n & 1) ? fhi(D[q]) : flo(D[q]);
        float r  = 1.0f / (1.0f + __expf(-(ga + bir + bhr)));
        float z  = 1.0f / (1.0f + __expf(-(gb + biz + bhz)));
        float nv = tanhf(gc + bin + r * (gd + bhn));
        hn[n] = (1.0f - z) * nv + z * hreg[n];
    }

    if (last) {
#pragma unroll
        for (int n = 0; n < 8; n++) {
            int node = n0 + n;
            if (node < NN) {
                int bg = __ldg(&batch[node]);
                atomicAdd(&g_pool[bg * 32 + lane], hn[n]);
                if (lane == 0) atomicAdd(&g_cnt[bg], 1.0f);
            }
        }
        return;
    }

    // overwrite h rows with hn, store g_h
#pragma unroll
    for (int n = 0; n < 8; n++) {
        sh[32 + lane][colbase + n] = hn[n];
        int node = n0 + n;
        if (node < NN) g_h[node * 32 + lane] = hn[n];
    }
    __syncwarp();

    // Y-GEMM: Y[j][o=lane] = sum_k hn[k] * W_MS[k][j*32+o]
    ull Yk[4][5];
#pragma unroll
    for (int q = 0; q < 4; q++)
#pragma unroll
        for (int j = 0; j < 5; j++) Yk[q][j] = 0ull;
#pragma unroll 8
    for (int k = 0; k < 32; k++) {
        ulonglong2 o01 = *(const ulonglong2*)&sh[32 + k][colbase];
        ulonglong2 o23 = *(const ulonglong2*)&sh[32 + k][colbase + 4];
#pragma unroll
        for (int j = 0; j < 5; j++) {
            ull w2 = dup2(__ldg(&W_MS[k * 160 + j * 32 + lane]));
            Yk[0][j] = ffma2(o01.x, w2, Yk[0][j]);
            Yk[1][j] = ffma2(o01.y, w2, Yk[1][j]);
            Yk[2][j] = ffma2(o23.x, w2, Yk[2][j]);
            Yk[3][j] = ffma2(o23.y, w2, Yk[3][j]);
        }
    }
#pragma unroll
    for (int n = 0; n < 8; n++) {
        int node = n0 + n;
        if (node < NN) {
#pragma unroll
            for (int j = 0; j < 5; j++) {
                float v = (n & 1) ? fhi(Yk[n >> 1][j]) : flo(Yk[n >> 1][j]);
                g_Y[(size_t)node * 160 + j * 32 + lane] = v;
            }
        }
    }
}

// ---------------- K_final ----------------
__global__ void k_final(const float* __restrict__ w,   // [2,32]
                        const float* __restrict__ b,   // [2]
                        float* __restrict__ out) {     // [G,2]
    int g = blockIdx.x * blockDim.x + threadIdx.x;
    if (g >= GG) return;
    float inv = 1.0f / fmaxf(g_cnt[g], 1.0f);
    float l0 = b[0], l1 = b[1];
#pragma unroll
    for (int d = 0; d < 32; d++) {
        float p = g_pool[g * 32 + d] * inv;
        l0 += p * w[d];
        l1 += p * w[32 + d];
    }
    float mx  = fmaxf(l0, l1);
    float lse = mx + logf(__expf(l0 - mx) + __expf(l1 - mx));
    out[g * 2 + 0] = l0 - lse;
    out[g * 2 + 1] = l1 - lse;
}

// ---------------- launch ----------------
extern "C" void kernel_launch(void* const* d_in, const int* in_sizes, int n_in,
                              void* d_out, int out_size) {
    const float* x        = (const float*)d_in[0];
    const float* edge_attr= (const float*)d_in[1];
    const float* lin0_w   = (const float*)d_in[2];
    const float* lin0_b   = (const float*)d_in[3];
    const float* nn_w     = (const float*)d_in[4];
    const float* nn_b     = (const float*)d_in[5];
    const float* root_w   = (const float*)d_in[6];
    const float* conv_b   = (const float*)d_in[7];
    const float* gru_wi   = (const float*)d_in[8];
    const float* gru_wh   = (const float*)d_in[9];
    const float* gru_bi   = (const float*)d_in[10];
    const float* gru_bh   = (const float*)d_in[11];
    const float* lin1_w   = (const float*)d_in[12];
    const float* lin1_b   = (const float*)d_in[13];
    const int*   edge_idx = (const int*)d_in[14];
    const int*   batch    = (const int*)d_in[15];
    float* out = (float*)d_out;

    const int TPB = 256;
    const int nodeBlocks = (NN + 63) / 64;                      // 782
    const int edgeWarpBlocks = ((EE / 4) * 32 + TPB - 1) / TPB; // 3125
    const int packBlocks = (GG * 32 + TPB - 1) / TPB;           // 256

    k_pack<<<packBlocks, TPB>>>(gru_wi, gru_wh, nn_w, nn_b);
    k_init<<<nodeBlocks, TPB>>>(x, lin0_w, lin0_b);

    for (int round = 0; round < 3; round++) {
        k_edge<<<edgeWarpBlocks, TPB>>>(edge_idx, edge_attr);
        k_node<<<nodeBlocks, TPB>>>(root_w, conv_b, gru_bi, gru_bh, batch, round == 2);
    }

    k_final<<<(GG + TPB - 1) / TPB, TPB>>>(lin1_w, lin1_b, out);
}

// round 16
// speedup vs baseline: 1.0165x; 1.0165x over previous
#include <cuda_runtime.h>
#include <math.h>

#define NN   50000
#define EE   100000
#define GG   2048

typedef unsigned long long ull;

// ---------------- device scratch ----------------
__device__ float g_h[NN * 32];
__device__ __align__(16) float g_aggr[NN * 32];
__device__ __align__(16) float g_Y[(size_t)NN * 160];   // [node][j*32+o]
__device__ float g_pool[GG * 32];
__device__ float g_cnt[GG];

// weight tables
__device__ __align__(16) float P_MS[5120];   // pair-packed for k_init
__device__ float W_G[64 * 96];               // k-major GRU (8-node k_node)
__device__ float W_MS[32 * 160];             // k-major msg (8-node k_node)
__device__ __align__(16) float P_RW[1024];   // packed root_w (last k_node)
__device__ __align__(16) float P_WG[6144];   // packed fused GRU (last k_node)

// ---------------- f32x2 helpers ----------------
__device__ __forceinline__ ull ffma2(ull a, ull b, ull c) {
    ull d;
    asm("fma.rn.f32x2 %0, %1, %2, %3;" : "=l"(d) : "l"(a), "l"(b), "l"(c));
    return d;
}
__device__ __forceinline__ ull dup2(float w) {
    ull r;
    asm("mov.b64 %0, {%1, %1};" : "=l"(r) : "f"(w));
    return r;
}
__device__ __forceinline__ float flo(ull v) { return __uint_as_float((unsigned)v); }
__device__ __forceinline__ float fhi(ull v) { return __uint_as_float((unsigned)(v >> 32)); }
__device__ __forceinline__ float psum(ull v) { return flo(v) + fhi(v); }

// ---------------- K_pack: zero pool + build all weight tables ----------------
__global__ void k_pack(const float* __restrict__ root_w, // [32,32]
                       const float* __restrict__ wi,     // [96,32]
                       const float* __restrict__ wh,     // [96,32]
                       const float* __restrict__ nn_w,   // [1024,4]
                       const float* __restrict__ nn_b) { // [1024]
    int gid = blockIdx.x * blockDim.x + threadIdx.x;
    if (gid < GG * 32) g_pool[gid] = 0.0f;
    if (gid < GG) g_cnt[gid] = 0.0f;

    if (gid < 6144) {                        // W_G
        int k = gid / 96, g = gid % 96;
        W_G[gid] = (k < 32) ? wi[g * 32 + k] : wh[g * 32 + (k - 32)];
    } else if (gid < 11264) {                // W_MS
        int t2 = gid - 6144;
        int k = t2 / 160, jo = t2 % 160;
        int j = jo >> 5, o = jo & 31;
        W_MS[t2] = (j < 4) ? nn_w[(k * 32 + o) * 4 + j] : nn_b[k * 32 + o];
    } else if (gid < 16384) {                // P_MS (pair-packed for k_init)
        int t2 = gid - 11264;
        int pos = t2 & 3;
        int tmp = t2 >> 2;
        int lane = tmp & 31;
        int j = (tmp >> 5) % 5;
        int i4 = (tmp >> 5) / 5;
        int i = i4 * 4 + pos;
        P_MS[t2] = (j < 4) ? nn_w[(i * 32 + lane) * 4 + j] : nn_b[i * 32 + lane];
    } else if (gid < 17408) {                // P_RW
        int t2 = gid - 16384;
        int pos = t2 & 3, o = (t2 >> 2) & 31, i4 = t2 >> 7;
        P_RW[t2] = root_w[(i4 * 4 + pos) * 32 + o];
    } else if (gid < 23552) {                // P_WG (fused GRU, 64-dim [m;h])
        int t2 = gid - 17408;
        int pos = t2 & 3;
        int tmp = t2 >> 2;
        int lane = tmp & 31;
        int gk = (tmp >> 5) % 3;
        int d4 = (tmp >> 5) / 3;
        int d = d4 * 4 + pos;
        int k = gk * 32 + lane;
        P_WG[t2] = (d < 32) ? wi[k * 32 + d] : wh[k * 32 + (d - 32)];
    }
}

// ---------------- K_init (R5 version): h0 = relu(lin0); Y0; zero aggr ----------------
__global__ __launch_bounds__(256, 2) void k_init(const float* __restrict__ x,
                                                 const float* __restrict__ w,   // [32,11]
                                                 const float* __restrict__ b) { // [32]
    __shared__ __align__(16) float hsm[8][8][32];
    int t = threadIdx.x, wrp = t >> 5, lane = t & 31;
    int n0 = blockIdx.x * 64 + wrp * 8;
    float (*row)[32] = hsm[wrp];

    float bias = __ldg(&b[lane]);
    float wv[11];
#pragma unroll
    for (int f = 0; f < 11; f++) wv[f] = __ldg(&w[lane * 11 + f]);

    float hn[8];
#pragma unroll
    for (int n = 0; n < 8; n++) {
        int node = n0 + n;
        float s = bias;
        if (node < NN) {
#pragma unroll
            for (int f = 0; f < 11; f++) s += __ldg(&x[node * 11 + f]) * wv[f];
        }
        hn[n] = fmaxf(s, 0.0f);
        row[n][lane] = hn[n];
    }
    __syncwarp();

    ull y[8][5];
#pragma unroll
    for (int n = 0; n < 8; n++)
#pragma unroll
        for (int j = 0; j < 5; j++) y[n][j] = 0ull;

#pragma unroll
    for (int i4 = 0; i4 < 8; i4++) {
        ulonglong2 mw[5];
#pragma unroll
        for (int j = 0; j < 5; j++)
            mw[j] = *(const ulonglong2*)&P_MS[((i4 * 5 + j) * 32 + lane) * 4];
#pragma unroll
        for (int n = 0; n < 8; n++) {
            ulonglong2 h2 = *(const ulonglong2*)&row[n][i4 * 4];
#pragma unroll
            for (int j = 0; j < 5; j++) {
                y[n][j] = ffma2(h2.x, mw[j].x, y[n][j]);
                y[n][j] = ffma2(h2.y, mw[j].y, y[n][j]);
            }
        }
    }
#pragma unroll
    for (int n = 0; n < 8; n++) {
        int node = n0 + n;
        if (node >= NN) break;
        g_h[node * 32 + lane] = hn[n];
        g_aggr[node * 32 + lane] = 0.0f;
        float* yb = &g_Y[(size_t)node * 160];
#pragma unroll
        for (int j = 0; j < 5; j++) yb[j * 32 + lane] = psum(y[n][j]);
    }
}

// ---------------- K_edge (R14): 4 edges/warp, 8 lanes/edge, v4 RED ----------------
__global__ void k_edge(const int* __restrict__ ei,        // [2,E]
                       const float* __restrict__ ea) {    // [E,4]
    int gt   = blockIdx.x * blockDim.x + threadIdx.x;
    int wrp  = gt >> 5;
    int lane = gt & 31;
    int e    = wrp * 4 + (lane >> 3);
    int q    = lane & 7;
    if (e >= EE) return;

    int s = __ldg(&ei[e]);
    int d = __ldg(&ei[EE + e]);
    float4 a = __ldg(&reinterpret_cast<const float4*>(ea)[e]);

    const float4* yb = reinterpret_cast<const float4*>(g_Y + (size_t)s * 160);
    float4 v0 = __ldg(&yb[q]);
    float4 v1 = __ldg(&yb[8 + q]);
    float4 v2 = __ldg(&yb[16 + q]);
    float4 v3 = __ldg(&yb[24 + q]);
    float4 vb = __ldg(&yb[32 + q]);

    float4 m;
    m.x = vb.x + a.x * v0.x + a.y * v1.x + a.z * v2.x + a.w * v3.x;
    m.y = vb.y + a.x * v0.y + a.y * v1.y + a.z * v2.y + a.w * v3.y;
    m.z = vb.z + a.x * v0.z + a.y * v1.z + a.z * v2.z + a.w * v3.z;
    m.w = vb.w + a.x * v0.w + a.y * v1.w + a.z * v2.w + a.w * v3.w;

    float* dst = g_aggr + (size_t)d * 32 + q * 4;
    asm volatile("red.global.add.v4.f32 [%0], {%1, %2, %3, %4};"
                 :: "l"(dst), "f"(m.x), "f"(m.y), "f"(m.z), "f"(m.w)
                 : "memory");
}

// ---------------- K_node_main (R7, non-last only): 8 warps x 8 nodes ----------------
__global__ __launch_bounds__(256, 2) void k_node_main(const float* __restrict__ root_w, // [32,32]
                                                      const float* __restrict__ conv_b, // [32]
                                                      const float* __restrict__ bi,     // [96]
                                                      const float* __restrict__ bh) {   // [96]
    __shared__ __align__(16) float sh[64][68];
    int t = threadIdx.x, wrp = t >> 5, lane = t & 31;
    int n0 = blockIdx.x * 64 + wrp * 8;
    int colbase = wrp * 8;

    float hreg[8], areg[8];
#pragma unroll
    for (int n = 0; n < 8; n++) {
        int node = n0 + n;
        hreg[n] = (node < NN) ? g_h[node * 32 + lane] : 0.0f;
        sh[32 + lane][colbase + n] = hreg[n];
    }
#pragma unroll
    for (int n = 0; n < 8; n++) {
        int node = n0 + n;
        areg[n] = (node < NN) ? __ldg(&g_aggr[node * 32 + lane]) : 0.0f;
    }
    __syncwarp();

    // --- root matvec ---
    ull R[4];
#pragma unroll
    for (int q = 0; q < 4; q++) R[q] = 0ull;
#pragma unroll 8
    for (int k = 0; k < 32; k++) {
        ulonglong2 o01 = *(const ulonglong2*)&sh[32 + k][colbase];
        ulonglong2 o23 = *(const ulonglong2*)&sh[32 + k][colbase + 4];
        ull w2 = dup2(__ldg(&root_w[k * 32 + lane]));
        R[0] = ffma2(o01.x, w2, R[0]);
        R[1] = ffma2(o01.y, w2, R[1]);
        R[2] = ffma2(o23.x, w2, R[2]);
        R[3] = ffma2(o23.y, w2, R[3]);
    }
    float cb = __ldg(&conv_b[lane]);
#pragma unroll
    for (int n = 0; n < 8; n++) {
        float r = (n & 1) ? fhi(R[n >> 1]) : flo(R[n >> 1]);
        float m = fmaxf(r + areg[n] + cb, 0.0f);
        sh[lane][colbase + n] = m;
        int node = n0 + n;
        if (node < NN) g_aggr[node * 32 + lane] = 0.0f;   // pre-zero for next round
    }
    __syncwarp();

    // --- GRU GEMMs ---
    ull A[4], B[4], C[4], D[4];
#pragma unroll
    for (int q = 0; q < 4; q++) { A[q] = B[q] = C[q] = D[q] = 0ull; }
#pragma unroll 8
    for (int k = 0; k < 32; k++) {            // m rows
        ulonglong2 o01 = *(const ulonglong2*)&sh[k][colbase];
        ulonglong2 o23 = *(const ulonglong2*)&sh[k][colbase + 4];
        ull wr = dup2(__ldg(&W_G[k * 96 + lane]));
        ull wz = dup2(__ldg(&W_G[k * 96 + 32 + lane]));
        ull wn = dup2(__ldg(&W_G[k * 96 + 64 + lane]));
        A[0] = ffma2(o01.x, wr, A[0]); A[1] = ffma2(o01.y, wr, A[1]);
        A[2] = ffma2(o23.x, wr, A[2]); A[3] = ffma2(o23.y, wr, A[3]);
        B[0] = ffma2(o01.x, wz, B[0]); B[1] = ffma2(o01.y, wz, B[1]);
        B[2] = ffma2(o23.x, wz, B[2]); B[3] = ffma2(o23.y, wz, B[3]);
        C[0] = ffma2(o01.x, wn, C[0]); C[1] = ffma2(o01.y, wn, C[1]);
        C[2] = ffma2(o23.x, wn, C[2]); C[3] = ffma2(o23.y, wn, C[3]);
    }
#pragma unroll 8
    for (int k = 32; k < 64; k++) {           // h rows
        ulonglong2 o01 = *(const ulonglong2*)&sh[k][colbase];
        ulonglong2 o23 = *(const ulonglong2*)&sh[k][colbase + 4];
        ull wr = dup2(__ldg(&W_G[k * 96 + lane]));
        ull wz = dup2(__ldg(&W_G[k * 96 + 32 + lane]));
        ull wn = dup2(__ldg(&W_G[k * 96 + 64 + lane]));
        A[0] = ffma2(o01.x, wr, A[0]); A[1] = ffma2(o01.y, wr, A[1]);
        A[2] = ffma2(o23.x, wr, A[2]); A[3] = ffma2(o23.y, wr, A[3]);
        B[0] = ffma2(o01.x, wz, B[0]); B[1] = ffma2(o01.y, wz, B[1]);
        B[2] = ffma2(o23.x, wz, B[2]); B[3] = ffma2(o23.y, wz, B[3]);
        D[0] = ffma2(o01.x, wn, D[0]); D[1] = ffma2(o01.y, wn, D[1]);
        D[2] = ffma2(o23.x, wn, D[2]); D[3] = ffma2(o23.y, wn, D[3]);
    }

    float bir = __ldg(&bi[lane]), biz = __ldg(&bi[lane + 32]), bin = __ldg(&bi[lane + 64]);
    float bhr = __ldg(&bh[lane]), bhz = __ldg(&bh[lane + 32]), bhn = __ldg(&bh[lane + 64]);

    float hn[8];
#pragma unroll
    for (int n = 0; n < 8; n++) {
        int q = n >> 1;
        float ga = (n & 1) ? fhi(A[q]) : flo(A[q]);
        float gb = (n & 1) ? fhi(B[q]) : flo(B[q]);
        float gc = (n & 1) ? fhi(C[q]) : flo(C[q]);
        float gd = (n & 1) ? fhi(D[q]) : flo(D[q]);
        float r  = 1.0f / (1.0f + __expf(-(ga + bir + bhr)));
        float z  = 1.0f / (1.0f + __expf(-(gb + biz + bhz)));
        float nv = tanhf(gc + bin + r * (gd + bhn));
        hn[n] = (1.0f - z) * nv + z * hreg[n];
    }

    // overwrite h rows with hn, store g_h
#pragma unroll
    for (int n = 0; n < 8; n++) {
        sh[32 + lane][colbase + n] = hn[n];
        int node = n0 + n;
        if (node < NN) g_h[node * 32 + lane] = hn[n];
    }
    __syncwarp();

    // Y-GEMM
    ull Yk[4][5];
#pragma unroll
    for (int q = 0; q < 4; q++)
#pragma unroll
        for (int j = 0; j < 5; j++) Yk[q][j] = 0ull;
#pragma unroll 8
    for (int k = 0; k < 32; k++) {
        ulonglong2 o01 = *(const ulonglong2*)&sh[32 + k][colbase];
        ulonglong2 o23 = *(const ulonglong2*)&sh[32 + k][colbase + 4];
#pragma unroll
        for (int j = 0; j < 5; j++) {
            ull w2 = dup2(__ldg(&W_MS[k * 160 + j * 32 + lane]));
            Yk[0][j] = ffma2(o01.x, w2, Yk[0][j]);
            Yk[1][j] = ffma2(o01.y, w2, Yk[1][j]);
            Yk[2][j] = ffma2(o23.x, w2, Yk[2][j]);
            Yk[3][j] = ffma2(o23.y, w2, Yk[3][j]);
        }
    }
#pragma unroll
    for (int n = 0; n < 8; n++) {
        int node = n0 + n;
        if (node < NN) {
#pragma unroll
            for (int j = 0; j < 5; j++) {
                float v = (n & 1) ? fhi(Yk[n >> 1][j]) : flo(Yk[n >> 1][j]);
                g_Y[(size_t)node * 160 + j * 32 + lane] = v;
            }
        }
    }
}

// ---------------- K_node_last (R6 4-node variant, pool only) ----------------
// 8 warps, 4 nodes/warp -> 32 nodes/block; 3 blocks/SM. No aggr re-zero, no Y.
__global__ __launch_bounds__(256, 3) void k_node_last(const float* __restrict__ conv_b, // [32]
                                                      const float* __restrict__ bi,     // [96]
                                                      const float* __restrict__ bh,     // [96]
                                                      const int* __restrict__ batch) {
    __shared__ __align__(16) float mh[8][4][64];
    int t = threadIdx.x, wrp = t >> 5, lane = t & 31;
    int n0 = blockIdx.x * 32 + wrp * 4;
    float (*row)[64] = mh[wrp];

#pragma unroll
    for (int n = 0; n < 4; n++) {
        int node = n0 + n;
        row[n][32 + lane] = (node < NN) ? g_h[node * 32 + lane] : 0.0f;
    }
    __syncwarp();

    // --- root mat-vec ---
    ull acc[4];
#pragma unroll
    for (int n = 0; n < 4; n++) acc[n] = 0ull;
#pragma unroll
    for (int i4 = 0; i4 < 8; i4++) {
        ulonglong2 wv = *(const ulonglong2*)&P_RW[(i4 * 32 + lane) * 4];
#pragma unroll
        for (int n = 0; n < 4; n++) {
            ulonglong2 h2 = *(const ulonglong2*)&row[n][32 + i4 * 4];
            acc[n] = ffma2(h2.x, wv.x, acc[n]);
            acc[n] = ffma2(h2.y, wv.y, acc[n]);
        }
    }
    float cb = __ldg(&conv_b[lane]);
#pragma unroll
    for (int n = 0; n < 4; n++) {
        int node = n0 + n;
        float a = (node < NN) ? g_aggr[node * 32 + lane] : 0.0f;
        row[n][lane] = fmaxf(psum(acc[n]) + a + cb, 0.0f);
    }
    __syncwarp();

    // --- fused GRU over 64-dim [m;h] ---
    ull A[4], B[4], C[4], D[4];
#pragma unroll
    for (int n = 0; n < 4; n++) { A[n] = B[n] = C[n] = D[n] = 0ull; }
#pragma unroll
    for (int d4 = 0; d4 < 16; d4++) {
        ulonglong2 wr = *(const ulonglong2*)&P_WG[((d4 * 3 + 0) * 32 + lane) * 4];
        ulonglong2 wz = *(const ulonglong2*)&P_WG[((d4 * 3 + 1) * 32 + lane) * 4];
        ulonglong2 wn = *(const ulonglong2*)&P_WG[((d4 * 3 + 2) * 32 + lane) * 4];
#pragma unroll
        for (int n = 0; n < 4; n++) {
            ulonglong2 v = *(const ulonglong2*)&row[n][d4 * 4];
            A[n] = ffma2(v.x, wr.x, A[n]);
            A[n] = ffma2(v.y, wr.y, A[n]);
            B[n] = ffma2(v.x, wz.x, B[n]);
            B[n] = ffma2(v.y, wz.y, B[n]);
            if (d4 < 8) {
                C[n] = ffma2(v.x, wn.x, C[n]);
                C[n] = ffma2(v.y, wn.y, C[n]);
            } else {
                D[n] = ffma2(v.x, wn.x, D[n]);
                D[n] = ffma2(v.y, wn.y, D[n]);
            }
        }
    }
    float bir = __ldg(&bi[lane]), biz = __ldg(&bi[lane + 32]), bin = __ldg(&bi[lane + 64]);
    float bhr = __ldg(&bh[lane]), bhz = __ldg(&bh[lane + 32]), bhn = __ldg(&bh[lane + 64]);

#pragma unroll
    for (int n = 0; n < 4; n++) {
        int node = n0 + n;
        if (node >= NN) break;
        float h  = row[n][32 + lane];
        float ra = psum(A[n]) + bir + bhr;
        float za = psum(B[n]) + biz + bhz;
        float cn = psum(C[n]) + bin;
        float dn = psum(D[n]) + bhn;
        float r  = 1.0f / (1.0f + __expf(-ra));
        float z  = 1.0f / (1.0f + __expf(-za));
        float nv = tanhf(cn + r * dn);
        float hn = (1.0f - z) * nv + z * h;
        int bg = __ldg(&batch[node]);
        atomicAdd(&g_pool[bg * 32 + lane], hn);
        if (lane == 0) atomicAdd(&g_cnt[bg], 1.0f);
    }
}

// ---------------- K_final ----------------
__global__ void k_final(const float* __restrict__ w,   // [2,32]
                        const float* __restrict__ b,   // [2]
                        float* __restrict__ out) {     // [G,2]
    int g = blockIdx.x * blockDim.x + threadIdx.x;
    if (g >= GG) return;
    float inv = 1.0f / fmaxf(g_cnt[g], 1.0f);
    float l0 = b[0], l1 = b[1];
#pragma unroll
    for (int d = 0; d < 32; d++) {
        float p = g_pool[g * 32 + d] * inv;
        l0 += p * w[d];
        l1 += p * w[32 + d];
    }
    float mx  = fmaxf(l0, l1);
    float lse = mx + logf(__expf(l0 - mx) + __expf(l1 - mx));
    out[g * 2 + 0] = l0 - lse;
    out[g * 2 + 1] = l1 - lse;
}

// ---------------- launch ----------------
extern "C" void kernel_launch(void* const* d_in, const int* in_sizes, int n_in,
                              void* d_out, int out_size) {
    const float* x        = (const float*)d_in[0];
    const float* edge_attr= (const float*)d_in[1];
    const float* lin0_w   = (const float*)d_in[2];
    const float* lin0_b   = (const float*)d_in[3];
    const float* nn_w     = (const float*)d_in[4];
    const float* nn_b     = (const float*)d_in[5];
    const float* root_w   = (const float*)d_in[6];
    const float* conv_b   = (const float*)d_in[7];
    const float* gru_wi   = (const float*)d_in[8];
    const float* gru_wh   = (const float*)d_in[9];
    const float* gru_bi   = (const float*)d_in[10];
    const float* gru_bh   = (const float*)d_in[11];
    const float* lin1_w   = (const float*)d_in[12];
    const float* lin1_b   = (const float*)d_in[13];
    const int*   edge_idx = (const int*)d_in[14];
    const int*   batch    = (const int*)d_in[15];
    float* out = (float*)d_out;

    const int TPB = 256;
    const int nodeBlocks64 = (NN + 63) / 64;                    // 782
    const int nodeBlocks32 = (NN + 31) / 32;                    // 1563
    const int edgeWarpBlocks = ((EE / 4) * 32 + TPB - 1) / TPB; // 3125
    const int packBlocks = (GG * 32 + TPB - 1) / TPB;           // 256

    k_pack<<<packBlocks, TPB>>>(root_w, gru_wi, gru_wh, nn_w, nn_b);
    k_init<<<nodeBlocks64, TPB>>>(x, lin0_w, lin0_b);

    for (int round = 0; round < 2; round++) {
        k_edge<<<edgeWarpBlocks, TPB>>>(edge_idx, edge_attr);
        k_node_main<<<nodeBlocks64, TPB>>>(root_w, conv_b, gru_bi, gru_bh);
    }
    k_edge<<<edgeWarpBlocks, TPB>>>(edge_idx, edge_attr);
    k_node_last<<<nodeBlocks32, TPB>>>(conv_b, gru_bi, gru_bh, batch);

    k_final<<<(GG + TPB - 1) / TPB, TPB>>>(lin1_w, lin1_b, out);
}

// round 17
// speedup vs baseline: 1.0417x; 1.0249x over previous
#include <cuda_runtime.h>
#include <math.h>

#define NN   50000
#define EE   100000
#define GG   2048

typedef unsigned long long ull;

// ---------------- device scratch ----------------
__device__ float g_h[NN * 32];
__device__ __align__(16) float g_aggr[NN * 32];
__device__ __align__(16) float g_Y[(size_t)NN * 160];   // [node][j*32+o]
__device__ float g_pool[GG * 32];
__device__ float g_cnt[GG];

// packed weights (16B chunks of 4 input-dims)
__device__ __align__(16) float P_RW[1024];   // root_w: [(i4*32+o)*4 + (i&3)]
__device__ __align__(16) float P_WG[6144];   // fused GRU: [((d4*3+g)*32+lane)*4 + (d&3)]
__device__ __align__(16) float P_MS[5120];   // 5 msg mats: [((i4*5+j)*32+lane)*4 + (i&3)]

// ---------------- f32x2 helpers ----------------
__device__ __forceinline__ ull ffma2(ull a, ull b, ull c) {
    ull d;
    asm("fma.rn.f32x2 %0, %1, %2, %3;" : "=l"(d) : "l"(a), "l"(b), "l"(c));
    return d;
}
__device__ __forceinline__ float flo(ull v) { return __uint_as_float((unsigned)v); }
__device__ __forceinline__ float fhi(ull v) { return __uint_as_float((unsigned)(v >> 32)); }
__device__ __forceinline__ float psum(ull v) { return flo(v) + fhi(v); }

// ---------------- K_pack: zero pool + build packed weights (R14) ----------------
__global__ void k_pack(const float* __restrict__ root_w,
                       const float* __restrict__ wi,
                       const float* __restrict__ wh,
                       const float* __restrict__ nn_w,
                       const float* __restrict__ nn_b) {
    int gid = blockIdx.x * blockDim.x + threadIdx.x;
    if (gid < GG * 32) g_pool[gid] = 0.0f;
    if (gid < GG) g_cnt[gid] = 0.0f;

    if (gid < 1024) {                        // root_w [i*32+o] -> P_RW
        int pos = gid & 3, o = (gid >> 2) & 31, i4 = gid >> 7;
        P_RW[gid] = root_w[(i4 * 4 + pos) * 32 + o];
    } else if (gid < 1024 + 6144) {          // fused GRU weights
        int t2 = gid - 1024;
        int pos = t2 & 3;
        int tmp = t2 >> 2;
        int lane = tmp & 31;
        int gk = (tmp >> 5) % 3;
        int d4 = (tmp >> 5) / 3;
        int d = d4 * 4 + pos;
        int k = gk * 32 + lane;
        P_WG[t2] = (d < 32) ? wi[k * 32 + d] : wh[k * 32 + (d - 32)];
    } else if (gid < 7168 + 5120) {          // 5 message matrices
        int t2 = gid - 7168;
        int pos = t2 & 3;
        int tmp = t2 >> 2;
        int lane = tmp & 31;
        int j = (tmp >> 5) % 5;
        int i4 = (tmp >> 5) / 5;
        int i = i4 * 4 + pos;
        P_MS[t2] = (j < 4) ? nn_w[(i * 32 + lane) * 4 + j] : nn_b[i * 32 + lane];
    }
}

// ---------------- K_init (R14): h0 = relu(lin0); Y0 = h0 @ M_j ; zero aggr ----------------
// 8 warps, 8 nodes/warp -> 64 nodes/block
__global__ __launch_bounds__(256, 2) void k_init(const float* __restrict__ x,
                                                 const float* __restrict__ w,   // [32,11]
                                                 const float* __restrict__ b) { // [32]
    __shared__ __align__(16) float hsm[8][8][32];
    int t = threadIdx.x, wrp = t >> 5, lane = t & 31;
    int n0 = blockIdx.x * 64 + wrp * 8;
    float (*row)[32] = hsm[wrp];

    float bias = __ldg(&b[lane]);
    float wv[11];
#pragma unroll
    for (int f = 0; f < 11; f++) wv[f] = __ldg(&w[lane * 11 + f]);

    float hn[8];
#pragma unroll
    for (int n = 0; n < 8; n++) {
        int node = n0 + n;
        float s = bias;
        if (node < NN) {
#pragma unroll
            for (int f = 0; f < 11; f++) s += __ldg(&x[node * 11 + f]) * wv[f];
        }
        hn[n] = fmaxf(s, 0.0f);
        row[n][lane] = hn[n];
    }
    __syncwarp();

    ull y[8][5];
#pragma unroll
    for (int n = 0; n < 8; n++)
#pragma unroll
        for (int j = 0; j < 5; j++) y[n][j] = 0ull;

#pragma unroll
    for (int i4 = 0; i4 < 8; i4++) {
        ulonglong2 mw[5];
#pragma unroll
        for (int j = 0; j < 5; j++)
            mw[j] = *(const ulonglong2*)&P_MS[((i4 * 5 + j) * 32 + lane) * 4];
#pragma unroll
        for (int n = 0; n < 8; n++) {
            ulonglong2 h2 = *(const ulonglong2*)&row[n][i4 * 4];
#pragma unroll
            for (int j = 0; j < 5; j++) {
                y[n][j] = ffma2(h2.x, mw[j].x, y[n][j]);
                y[n][j] = ffma2(h2.y, mw[j].y, y[n][j]);
            }
        }
    }
#pragma unroll
    for (int n = 0; n < 8; n++) {
        int node = n0 + n;
        if (node >= NN) break;
        g_h[node * 32 + lane] = hn[n];
        g_aggr[node * 32 + lane] = 0.0f;
        float* yb = &g_Y[(size_t)node * 160];
#pragma unroll
        for (int j = 0; j < 5; j++) yb[j * 32 + lane] = psum(y[n][j]);
    }
}

// ---------------- K_edge (R14): 4 edges/warp, 8 lanes/edge, v4 RED ----------------
__global__ void k_edge(const int* __restrict__ ei,        // [2,E]
                       const float* __restrict__ ea) {    // [E,4]
    int gt   = blockIdx.x * blockDim.x + threadIdx.x;
    int wrp  = gt >> 5;
    int lane = gt & 31;
    int e    = wrp * 4 + (lane >> 3);
    int q    = lane & 7;
    if (e >= EE) return;

    int s = __ldg(&ei[e]);
    int d = __ldg(&ei[EE + e]);
    float4 a = __ldg(&reinterpret_cast<const float4*>(ea)[e]);

    const float4* yb = reinterpret_cast<const float4*>(g_Y + (size_t)s * 160);
    float4 v0 = __ldg(&yb[q]);
    float4 v1 = __ldg(&yb[8 + q]);
    float4 v2 = __ldg(&yb[16 + q]);
    float4 v3 = __ldg(&yb[24 + q]);
    float4 vb = __ldg(&yb[32 + q]);

    float4 m;
    m.x = vb.x + a.x * v0.x + a.y * v1.x + a.z * v2.x + a.w * v3.x;
    m.y = vb.y + a.x * v0.y + a.y * v1.y + a.z * v2.y + a.w * v3.y;
    m.z = vb.z + a.x * v0.z + a.y * v1.z + a.z * v2.z + a.w * v3.z;
    m.w = vb.w + a.x * v0.w + a.y * v1.w + a.z * v2.w + a.w * v3.w;

    float* dst = g_aggr + (size_t)d * 32 + q * 4;
    asm volatile("red.global.add.v4.f32 [%0], {%1, %2, %3, %4};"
                 :: "l"(dst), "f"(m.x), "f"(m.y), "f"(m.z), "f"(m.w)
                 : "memory");
}

// ---------------- K_node_main (R14 k_node, non-last path only) ----------------
// 8 warps, 4 nodes/warp -> 32 nodes/block; 3 blocks/SM.
__global__ __launch_bounds__(256, 3) void k_node_main(const float* __restrict__ conv_b, // [32]
                                                      const float* __restrict__ bi,     // [96]
                                                      const float* __restrict__ bh) {   // [96]
    __shared__ __align__(16) float mh[8][4][64];
    int t = threadIdx.x, wrp = t >> 5, lane = t & 31;
    int n0 = blockIdx.x * 32 + wrp * 4;
    float (*row)[64] = mh[wrp];

    // stage h
#pragma unroll
    for (int n = 0; n < 4; n++) {
        int node = n0 + n;
        row[n][32 + lane] = (node < NN) ? g_h[node * 32 + lane] : 0.0f;
    }
    __syncwarp();

    // --- root mat-vec ---
    ull acc[4];
#pragma unroll
    for (int n = 0; n < 4; n++) acc[n] = 0ull;
#pragma unroll
    for (int i4 = 0; i4 < 8; i4++) {
        ulonglong2 wv = *(const ulonglong2*)&P_RW[(i4 * 32 + lane) * 4];
#pragma unroll
        for (int n = 0; n < 4; n++) {
            ulonglong2 h2 = *(const ulonglong2*)&row[n][32 + i4 * 4];
            acc[n] = ffma2(h2.x, wv.x, acc[n]);
            acc[n] = ffma2(h2.y, wv.y, acc[n]);
        }
    }
    float cb = __ldg(&conv_b[lane]);
#pragma unroll
    for (int n = 0; n < 4; n++) {
        int node = n0 + n;
        float a = 0.0f;
        if (node < NN) {
            a = g_aggr[node * 32 + lane];
            g_aggr[node * 32 + lane] = 0.0f;   // pre-zero for next round
        }
        row[n][lane] = fmaxf(psum(acc[n]) + a + cb, 0.0f);
    }
    __syncwarp();

    // --- fused GRU gates over 64-dim [m;h] ---
    ull A[4], B[4], C[4], D[4];
#pragma unroll
    for (int n = 0; n < 4; n++) { A[n] = B[n] = C[n] = D[n] = 0ull; }
#pragma unroll
    for (int d4 = 0; d4 < 16; d4++) {
        ulonglong2 wr = *(const ulonglong2*)&P_WG[((d4 * 3 + 0) * 32 + lane) * 4];
        ulonglong2 wz = *(const ulonglong2*)&P_WG[((d4 * 3 + 1) * 32 + lane) * 4];
        ulonglong2 wn = *(const ulonglong2*)&P_WG[((d4 * 3 + 2) * 32 + lane) * 4];
#pragma unroll
        for (int n = 0; n < 4; n++) {
            ulonglong2 v = *(const ulonglong2*)&row[n][d4 * 4];
            A[n] = ffma2(v.x, wr.x, A[n]);
            A[n] = ffma2(v.y, wr.y, A[n]);
            B[n] = ffma2(v.x, wz.x, B[n]);
            B[n] = ffma2(v.y, wz.y, B[n]);
            if (d4 < 8) {           // m-part -> inn
                C[n] = ffma2(v.x, wn.x, C[n]);
                C[n] = ffma2(v.y, wn.y, C[n]);
            } else {                // h-part -> hn
                D[n] = ffma2(v.x, wn.x, D[n]);
                D[n] = ffma2(v.y, wn.y, D[n]);
            }
        }
    }
    float bir = __ldg(&bi[lane]), biz = __ldg(&bi[lane + 32]), bin = __ldg(&bi[lane + 64]);
    float bhr = __ldg(&bh[lane]), bhz = __ldg(&bh[lane + 32]), bhn = __ldg(&bh[lane + 64]);

    float hn[4];
#pragma unroll
    for (int n = 0; n < 4; n++) {
        float h  = row[n][32 + lane];
        float ra = psum(A[n]) + bir + bhr;
        float za = psum(B[n]) + biz + bhz;
        float cn = psum(C[n]) + bin;
        float dn = psum(D[n]) + bhn;
        float r  = 1.0f / (1.0f + __expf(-ra));
        float z  = 1.0f / (1.0f + __expf(-za));
        float nv = tanhf(cn + r * dn);
        hn[n] = (1.0f - z) * nv + z * h;
    }

    // --- fused Y for next round ---
#pragma unroll
    for (int n = 0; n < 4; n++) row[n][lane] = hn[n];
    __syncwarp();

    ull y[4][5];
#pragma unroll
    for (int n = 0; n < 4; n++)
#pragma unroll
        for (int j = 0; j < 5; j++) y[n][j] = 0ull;
#pragma unroll
    for (int i4 = 0; i4 < 8; i4++) {
        ulonglong2 mw[5];
#pragma unroll
        for (int j = 0; j < 5; j++)
            mw[j] = *(const ulonglong2*)&P_MS[((i4 * 5 + j) * 32 + lane) * 4];
#pragma unroll
        for (int n = 0; n < 4; n++) {
            ulonglong2 h2 = *(const ulonglong2*)&row[n][i4 * 4];
#pragma unroll
            for (int j = 0; j < 5; j++) {
                y[n][j] = ffma2(h2.x, mw[j].x, y[n][j]);
                y[n][j] = ffma2(h2.y, mw[j].y, y[n][j]);
            }
        }
    }
#pragma unroll
    for (int n = 0; n < 4; n++) {
        int node = n0 + n;
        if (node >= NN) break;
        g_h[node * 32 + lane] = hn[n];
        float* yb = &g_Y[(size_t)node * 160];
#pragma unroll
        for (int j = 0; j < 5; j++) yb[j * 32 + lane] = psum(y[n][j]);
    }
}

// ---------------- K_node_last (R16-validated): pool only, no aggr zero, no Y ----------------
__global__ __launch_bounds__(256, 3) void k_node_last(const float* __restrict__ conv_b, // [32]
                                                      const float* __restrict__ bi,     // [96]
                                                      const float* __restrict__ bh,     // [96]
                                                      const int* __restrict__ batch) {
    __shared__ __align__(16) float mh[8][4][64];
    int t = threadIdx.x, wrp = t >> 5, lane = t & 31;
    int n0 = blockIdx.x * 32 + wrp * 4;
    float (*row)[64] = mh[wrp];

#pragma unroll
    for (int n = 0; n < 4; n++) {
        int node = n0 + n;
        row[n][32 + lane] = (node < NN) ? g_h[node * 32 + lane] : 0.0f;
    }
    __syncwarp();

    // --- root mat-vec ---
    ull acc[4];
#pragma unroll
    for (int n = 0; n < 4; n++) acc[n] = 0ull;
#pragma unroll
    for (int i4 = 0; i4 < 8; i4++) {
        ulonglong2 wv = *(const ulonglong2*)&P_RW[(i4 * 32 + lane) * 4];
#pragma unroll
        for (int n = 0; n < 4; n++) {
            ulonglong2 h2 = *(const ulonglong2*)&row[n][32 + i4 * 4];
            acc[n] = ffma2(h2.x, wv.x, acc[n]);
            acc[n] = ffma2(h2.y, wv.y, acc[n]);
        }
    }
    float cb = __ldg(&conv_b[lane]);
#pragma unroll
    for (int n = 0; n < 4; n++) {
        int node = n0 + n;
        float a = (node < NN) ? g_aggr[node * 32 + lane] : 0.0f;
        row[n][lane] = fmaxf(psum(acc[n]) + a + cb, 0.0f);
    }
    __syncwarp();

    // --- fused GRU over 64-dim [m;h] ---
    ull A[4], B[4], C[4], D[4];
#pragma unroll
    for (int n = 0; n < 4; n++) { A[n] = B[n] = C[n] = D[n] = 0ull; }
#pragma unroll
    for (int d4 = 0; d4 < 16; d4++) {
        ulonglong2 wr = *(const ulonglong2*)&P_WG[((d4 * 3 + 0) * 32 + lane) * 4];
        ulonglong2 wz = *(const ulonglong2*)&P_WG[((d4 * 3 + 1) * 32 + lane) * 4];
        ulonglong2 wn = *(const ulonglong2*)&P_WG[((d4 * 3 + 2) * 32 + lane) * 4];
#pragma unroll
        for (int n = 0; n < 4; n++) {
            ulonglong2 v = *(const ulonglong2*)&row[n][d4 * 4];
            A[n] = ffma2(v.x, wr.x, A[n]);
            A[n] = ffma2(v.y, wr.y, A[n]);
            B[n] = ffma2(v.x, wz.x, B[n]);
            B[n] = ffma2(v.y, wz.y, B[n]);
            if (d4 < 8) {
                C[n] = ffma2(v.x, wn.x, C[n]);
                C[n] = ffma2(v.y, wn.y, C[n]);
            } else {
                D[n] = ffma2(v.x, wn.x, D[n]);
                D[n] = ffma2(v.y, wn.y, D[n]);
            }
        }
    }
    float bir = __ldg(&bi[lane]), biz = __ldg(&bi[lane + 32]), bin = __ldg(&bi[lane + 64]);
    float bhr = __ldg(&bh[lane]), bhz = __ldg(&bh[lane + 32]), bhn = __ldg(&bh[lane + 64]);

#pragma unroll
    for (int n = 0; n < 4; n++) {
        int node = n0 + n;
        if (node >= NN) break;
        float h  = row[n][32 + lane];
        float ra = psum(A[n]) + bir + bhr;
        float za = psum(B[n]) + biz + bhz;
        float cn = psum(C[n]) + bin;
        float dn = psum(D[n]) + bhn;
        float r  = 1.0f / (1.0f + __expf(-ra));
        float z  = 1.0f / (1.0f + __expf(-za));
        float nv = tanhf(cn + r * dn);
        float hn = (1.0f - z) * nv + z * h;
        int bg = __ldg(&batch[node]);
        atomicAdd(&g_pool[bg * 32 + lane], hn);
        if (lane == 0) atomicAdd(&g_cnt[bg], 1.0f);
    }
}

// ---------------- K_final: logits + log_softmax ----------------
__global__ void k_final(const float* __restrict__ w,   // [2,32]
                        const float* __restrict__ b,   // [2]
                        float* __restrict__ out) {     // [G,2]
    int g = blockIdx.x * blockDim.x + threadIdx.x;
    if (g >= GG) return;
    float inv = 1.0f / fmaxf(g_cnt[g], 1.0f);
    float l0 = b[0], l1 = b[1];
#pragma unroll
    for (int d = 0; d < 32; d++) {
        float p = g_pool[g * 32 + d] * inv;
        l0 += p * w[d];
        l1 += p * w[32 + d];
    }
    float mx  = fmaxf(l0, l1);
    float lse = mx + logf(__expf(l0 - mx) + __expf(l1 - mx));
    out[g * 2 + 0] = l0 - lse;
    out[g * 2 + 1] = l1 - lse;
}

// ---------------- launch ----------------
extern "C" void kernel_launch(void* const* d_in, const int* in_sizes, int n_in,
                              void* d_out, int out_size) {
    const float* x        = (const float*)d_in[0];
    const float* edge_attr= (const float*)d_in[1];
    const float* lin0_w   = (const float*)d_in[2];
    const float* lin0_b   = (const float*)d_in[3];
    const float* nn_w     = (const float*)d_in[4];
    const float* nn_b     = (const float*)d_in[5];
    const float* root_w   = (const float*)d_in[6];
    const float* conv_b   = (const float*)d_in[7];
    const float* gru_wi   = (const float*)d_in[8];
    const float* gru_wh   = (const float*)d_in[9];
    const float* gru_bi   = (const float*)d_in[10];
    const float* gru_bh   = (const float*)d_in[11];
    const float* lin1_w   = (const float*)d_in[12];
    const float* lin1_b   = (const float*)d_in[13];
    const int*   edge_idx = (const int*)d_in[14];
    const int*   batch    = (const int*)d_in[15];
    float* out = (float*)d_out;

    const int TPB = 256;
    const int initBlocks = (NN + 63) / 64;                      // 782
    const int nodeBlocks = (NN + 31) / 32;                      // 1563
    const int edgeWarpBlocks = ((EE / 4) * 32 + TPB - 1) / TPB; // 3125
    const int packBlocks = (GG * 32 + TPB - 1) / TPB;           // 256

    k_pack<<<packBlocks, TPB>>>(root_w, gru_wi, gru_wh, nn_w, nn_b);
    k_init<<<initBlocks, TPB>>>(x, lin0_w, lin0_b);

    for (int round = 0; round < 2; round++) {
        k_edge<<<edgeWarpBlocks, TPB>>>(edge_idx, edge_attr);
        k_node_main<<<nodeBlocks, TPB>>>(conv_b, gru_bi, gru_bh);
    }
    k_edge<<<edgeWarpBlocks, TPB>>>(edge_idx, edge_attr);
    k_node_last<<<nodeBlocks, TPB>>>(conv_b, gru_bi, gru_bh, batch);

    k_final<<<(GG + TPB - 1) / TPB, TPB>>>(lin1_w, lin1_b, out);
}